// round 5
// baseline (speedup 1.0000x reference)
#include <cuda_runtime.h>
#include <cuda_fp16.h>

#define BATCH 8
#define M 4096
#define NPTS 4096
#define NSLICES 8
#define SLICE (NPTS / NSLICES)               // 512 gt points per block
#define ROWS_PB 32                           // rows per block (4 per warp)
#define RGROUPS (M / ROWS_PB)                // 128
#define NBLOCKS (BATCH * RGROUPS * NSLICES)  // 8192
#define NROWS (BATCH * M)                    // 32768

// f16-exact scale: round_to_f16(10*log2(e)) = 14.4296875.
// ex2 arg: 12 - C*d  =>  e = 2^12 * softmin weight; the 2^12 cancels in w/s.
#define C_F16 14.4296875f

__device__ float g_s[NROWS * NSLICES];   // per-(row, slice) sum of e
__device__ float g_w[NROWS * NSLICES];   // per-(row, slice) sum of e*d
__device__ float g_p2[64];

typedef unsigned long long ull;

__device__ __forceinline__ ull pack2(float lo, float hi) {
    ull r; asm("mov.b64 %0, {%1, %2};" : "=l"(r) : "f"(lo), "f"(hi)); return r;
}
__device__ __forceinline__ void unpack2(ull v, float& lo, float& hi) {
    asm("mov.b64 {%0, %1}, %2;" : "=f"(lo), "=f"(hi) : "l"(v));
}
__device__ __forceinline__ ull fma2(ull a, ull b, ull c) {
    ull r; asm("fma.rn.f32x2 %0, %1, %2, %3;" : "=l"(r) : "l"(a), "l"(b), "l"(c)); return r;
}
__device__ __forceinline__ ull add2(ull a, ull b) {
    ull r; asm("add.rn.f32x2 %0, %1, %2;" : "=l"(r) : "l"(a), "l"(b)); return r;
}
__device__ __forceinline__ ull mul2(ull a, ull b) {
    ull r; asm("mul.rn.f32x2 %0, %1, %2;" : "=l"(r) : "l"(a), "l"(b)); return r;
}
__device__ __forceinline__ float fsqrt_abs(float x) {
    float r; asm("sqrt.approx.f32 %0, %1;" : "=f"(r) : "f"(fabsf(x))); return r;
}
// two f32 -> packed f16x2 in one instruction
__device__ __forceinline__ __half2 halves2(float a, float b) {
    unsigned r; asm("cvt.rn.f16x2.f32 %0, %1, %2;" : "=r"(r) : "f"(a), "f"(b));
    return reinterpret_cast<__half2&>(r);
}
__device__ __forceinline__ __half2 ex2_h2(__half2 x) {
    unsigned xi = reinterpret_cast<unsigned&>(x), ri;
    asm("ex2.approx.f16x2 %0, %1;" : "=r"(ri) : "r"(xi));
    return reinterpret_cast<__half2&>(ri);
}
// 8-byte shared load of two adjacent floats, already packed as f32x2
__device__ __forceinline__ ull lds64(const float* p) {
    ull r; unsigned a = (unsigned)__cvta_generic_to_shared(p);
    asm("ld.shared.b64 %0, [%1];" : "=l"(r) : "r"(a));
    return r;
}

__global__ __launch_bounds__(256, 3)
void emd_main(const float* __restrict__ pred, const float* __restrict__ gt)
{
    __shared__ __align__(16) float spx[SLICE];
    __shared__ __align__(16) float spy[SLICE];
    __shared__ __align__(16) float spz[SLICE];

    const int bid = blockIdx.x;
    const int b   = bid / (RGROUPS * NSLICES);
    const int rem = bid % (RGROUPS * NSLICES);
    const int rg  = rem / NSLICES;
    const int sl  = rem % NSLICES;

    // Stage this slice's gt points (coalesced-ish: warp spans 384B per iter)
    const float* g = gt + ((size_t)b * NPTS + (size_t)sl * SLICE) * 3;
    for (int i = threadIdx.x; i < SLICE; i += 256) {
        spx[i] = g[3 * i + 0];
        spy[i] = g[3 * i + 1];
        spz[i] = g[3 * i + 2];
    }
    __syncthreads();

    const int warp = threadIdx.x >> 5;
    const int lane = threadIdx.x & 31;
    const int m0   = rg * ROWS_PB + warp * 4;   // this warp's 4 rows

    // Per-row duplicated packed constants: q = -2p (dup), p2 = |p|^2 (dup)
    ull qx2[4], qy2[4], qz2[4], p22[4];
    const float* p = pred + ((size_t)b * M + m0) * 3;
#pragma unroll
    for (int r = 0; r < 4; r++) {
        float px = __ldg(p + 3 * r + 0);   // uniform across warp -> broadcast
        float py = __ldg(p + 3 * r + 1);
        float pz = __ldg(p + 3 * r + 2);
        qx2[r] = pack2(-2.0f * px, -2.0f * px);
        qy2[r] = pack2(-2.0f * py, -2.0f * py);
        qz2[r] = pack2(-2.0f * pz, -2.0f * pz);
        float pp = fmaf(px, px, fmaf(py, py, pz * pz));
        p22[r] = pack2(pp, pp);
    }

    const __half2 hC = __float2half2_rn(-C_F16);
    const __half2 hB = __float2half2_rn(12.0f);
    const __half2 hZ = __float2half2_rn(0.0f);

    __half2 sh[4], wh[4];
    float sF[4], wF[4];
#pragma unroll
    for (int r = 0; r < 4; r++) { sh[r] = hZ; wh[r] = hZ; sF[r] = 0.0f; wF[r] = 0.0f; }

    // 8 point-pairs per lane; lane L handles points {2L+64j, 2L+64j+1}
#pragma unroll
    for (int j = 0; j < 8; j++) {
        const int n = 2 * lane + 64 * j;
        const ull axx = lds64(&spx[n]);
        const ull ayy = lds64(&spy[n]);
        const ull azz = lds64(&spz[n]);
        const ull g22 = fma2(axx, axx, fma2(ayy, ayy, mul2(azz, azz)));
#pragma unroll
        for (int r = 0; r < 4; r++) {
            ull t = add2(g22, p22[r]);
            t = fma2(qz2[r], azz, t);
            t = fma2(qy2[r], ayy, t);
            t = fma2(qx2[r], axx, t);             // packed d^2 for 2 points
            float d2lo, d2hi; unpack2(t, d2lo, d2hi);
            float dlo = fsqrt_abs(d2lo);
            float dhi = fsqrt_abs(d2hi);
            __half2 hd = halves2(dlo, dhi);
            __half2 e2 = ex2_h2(__hfma2(hd, hC, hB));   // 2^12 * exp(-d/T)
            sh[r] = __hadd2(sh[r], e2);                 // f16 accumulate
            wh[r] = __hfma2(e2, hd, wh[r]);
        }
        if (j == 3) {                                  // mid flush: <=4 terms/half
#pragma unroll
            for (int r = 0; r < 4; r++) {
                sF[r] += __low2float(sh[r]) + __high2float(sh[r]);
                wF[r] += __low2float(wh[r]) + __high2float(wh[r]);
                sh[r] = hZ; wh[r] = hZ;
            }
        }
    }
#pragma unroll
    for (int r = 0; r < 4; r++) {
        sF[r] += __low2float(sh[r]) + __high2float(sh[r]);
        wF[r] += __low2float(wh[r]) + __high2float(wh[r]);
    }

    // Warp-reduce (s, w) per row; this warp owns the row for this slice
#pragma unroll
    for (int r = 0; r < 4; r++) {
        float s = sF[r], w = wF[r];
#pragma unroll
        for (int o = 16; o; o >>= 1) {
            s += __shfl_xor_sync(0xffffffffu, s, o);
            w += __shfl_xor_sync(0xffffffffu, w, o);
        }
        if (lane == 0) {
            const int row = b * M + m0 + r;
            g_s[row * NSLICES + sl] = s;
            g_w[row * NSLICES + sl] = w;
        }
    }
}

__global__ void emd_combine(void)
{
    __shared__ float sm[16];
    const int row = blockIdx.x * 512 + threadIdx.x;   // 64 blocks x 512 = 32768
    float s = 0.0f, w = 0.0f;
#pragma unroll
    for (int k = 0; k < NSLICES; k++) {
        s += g_s[row * NSLICES + k];
        w += g_w[row * NSLICES + k];
    }
    float val = w / s;                    // per-row softmin-weighted distance
#pragma unroll
    for (int o = 16; o; o >>= 1)
        val += __shfl_xor_sync(0xffffffffu, val, o);
    if ((threadIdx.x & 31) == 0) sm[threadIdx.x >> 5] = val;
    __syncthreads();
    if (threadIdx.x < 16) {
        float v = sm[threadIdx.x];
#pragma unroll
        for (int o = 8; o; o >>= 1)
            v += __shfl_xor_sync(0xffffu, v, o);
        if (threadIdx.x == 0) g_p2[blockIdx.x] = v;
    }
}

__global__ void emd_final(float* __restrict__ out)
{
    __shared__ float sm[2];
    float v = g_p2[threadIdx.x];          // 64 threads
#pragma unroll
    for (int o = 16; o; o >>= 1)
        v += __shfl_xor_sync(0xffffffffu, v, o);
    if ((threadIdx.x & 31) == 0) sm[threadIdx.x >> 5] = v;
    __syncthreads();
    if (threadIdx.x == 0)
        out[0] = (sm[0] + sm[1]) * (1.0f / (float)NROWS);   // LOSS_WEIGHT = 1.0
}

extern "C" void kernel_launch(void* const* d_in, const int* in_sizes, int n_in,
                              void* d_out, int out_size)
{
    const float* pred = (const float*)d_in[0];  // [B, M, 3] fp32
    const float* gt   = (const float*)d_in[1];  // [B, N, 3] fp32
    float* out        = (float*)d_out;          // scalar fp32

    emd_main<<<NBLOCKS, 256>>>(pred, gt);
    emd_combine<<<64, 512>>>();
    emd_final<<<1, 64>>>(out);
}

// round 6
// speedup vs baseline: 1.0312x; 1.0312x over previous
#include <cuda_runtime.h>
#include <cuda_fp16.h>
#include <cstring>

#define BATCH 8
#define M 4096
#define NPTS 4096
#define NSLICES 8
#define SLICE (NPTS / NSLICES)               // 512 gt points per block
#define ROWS_PB 32                           // rows per block (4 per warp)
#define RGROUPS (M / ROWS_PB)                // 128
#define NBLOCKS (BATCH * RGROUPS * NSLICES)  // 8192
#define NROWS (BATCH * M)                    // 32768

// f16-exact scale: round_to_f16(10*log2(e)) = 14.4296875.
// ex2 arg: 12 - C*d  =>  e = 2^12 * softmin weight; the 2^12 cancels in w/s.
#define C_F16 14.4296875f

__device__ float g_s[NROWS * NSLICES];   // per-(row, slice) sum of e
__device__ float g_w[NROWS * NSLICES];   // per-(row, slice) sum of e*d
__device__ float g_p2[64];

typedef unsigned long long ull;

__device__ __forceinline__ ull pack2(float lo, float hi) {
    ull r; asm("mov.b64 %0, {%1, %2};" : "=l"(r) : "f"(lo), "f"(hi)); return r;
}
__device__ __forceinline__ ull fma2(ull a, ull b, ull c) {
    ull r; asm("fma.rn.f32x2 %0, %1, %2, %3;" : "=l"(r) : "l"(a), "l"(b), "l"(c)); return r;
}
__device__ __forceinline__ ull add2(ull a, ull b) {
    ull r; asm("add.rn.f32x2 %0, %1, %2;" : "=l"(r) : "l"(a), "l"(b)); return r;
}
// 8-byte shared load via precomputed 32-bit shared address (no per-call cvta)
__device__ __forceinline__ ull lds64(unsigned a) {
    ull r; asm("ld.shared.b64 %0, [%1];" : "=l"(r) : "r"(a)); return r;
}

// Fused per-unit tail: packed d2 (f32x2) -> abs -> sqrt x2 -> f16x2 d ->
// arg = 12 - C*d -> ex2 -> accumulate s += e, w += e*d (all f16x2).
// One asm block so ptxas coalesces the unpack movs into register pairing.
__device__ __forceinline__ void tail(ull t, unsigned hC, unsigned hB,
                                     unsigned& s, unsigned& w) {
    asm("{\n\t"
        ".reg .f32 lo, hi, alo, ahi, slo, shi;\n\t"
        ".reg .b32 hd, arg, e;\n\t"
        "mov.b64 {lo, hi}, %2;\n\t"
        "abs.f32 alo, lo;\n\t"
        "abs.f32 ahi, hi;\n\t"
        "sqrt.approx.f32 slo, alo;\n\t"
        "sqrt.approx.f32 shi, ahi;\n\t"
        "cvt.rn.f16x2.f32 hd, shi, slo;\n\t"
        "fma.rn.f16x2 arg, hd, %3, %4;\n\t"
        "ex2.approx.f16x2 e, arg;\n\t"
        "add.rn.f16x2 %0, %0, e;\n\t"
        "fma.rn.f16x2 %1, e, hd, %1;\n\t"
        "}"
        : "+r"(s), "+r"(w)
        : "l"(t), "r"(hC), "r"(hB));
}

__device__ __forceinline__ void flush_h2(unsigned& h, float& f) {
    __half2 v; memcpy(&v, &h, 4);
    f += __low2float(v) + __high2float(v);
    h = 0u;
}

__global__ __launch_bounds__(256, 3)
void emd_main(const float* __restrict__ pred, const float* __restrict__ gt)
{
    __shared__ __align__(16) float spx[SLICE];
    __shared__ __align__(16) float spy[SLICE];
    __shared__ __align__(16) float spz[SLICE];
    __shared__ __align__(16) float sg2[SLICE];

    const int bid = blockIdx.x;
    const int sl  = bid & (NSLICES - 1);
    const int rg  = (bid >> 3) & (RGROUPS - 1);
    const int b   = bid >> 10;

    // Stage slice with precomputed |g|^2
    const float* g = gt + ((size_t)b * NPTS + (size_t)sl * SLICE) * 3;
    for (int i = threadIdx.x; i < SLICE; i += 256) {
        float x = g[3 * i + 0];
        float y = g[3 * i + 1];
        float z = g[3 * i + 2];
        spx[i] = x; spy[i] = y; spz[i] = z;
        sg2[i] = fmaf(x, x, fmaf(y, y, z * z));
    }
    __syncthreads();

    const int warp = threadIdx.x >> 5;
    const int lane = threadIdx.x & 31;
    const int m0   = rg * ROWS_PB + warp * 4;   // this warp's 4 rows

    // Per-row duplicated packed constants: q = -2p (dup), p2 = |p|^2 (dup)
    ull qx2[4], qy2[4], qz2[4], p22[4];
    const float* p = pred + ((size_t)b * M + m0) * 3;
#pragma unroll
    for (int r = 0; r < 4; r++) {
        float px = __ldg(p + 3 * r + 0);
        float py = __ldg(p + 3 * r + 1);
        float pz = __ldg(p + 3 * r + 2);
        qx2[r] = pack2(-2.0f * px, -2.0f * px);
        qy2[r] = pack2(-2.0f * py, -2.0f * py);
        qz2[r] = pack2(-2.0f * pz, -2.0f * pz);
        float pp = fmaf(px, px, fmaf(py, py, pz * pz));
        p22[r] = pack2(pp, pp);
    }

    unsigned hC, hB;
    { __half2 t = __float2half2_rn(-C_F16); memcpy(&hC, &t, 4); }
    { __half2 t = __float2half2_rn(12.0f);  memcpy(&hB, &t, 4); }

    unsigned sh[4] = {0u, 0u, 0u, 0u};
    unsigned wh[4] = {0u, 0u, 0u, 0u};
    float sF[4] = {0.f, 0.f, 0.f, 0.f};
    float wF[4] = {0.f, 0.f, 0.f, 0.f};

    // Shared addresses hoisted once; per-j offsets fold into LDS immediates
    const unsigned off = 8u * (unsigned)lane;
    const unsigned ax_a = (unsigned)__cvta_generic_to_shared(spx) + off;
    const unsigned ay_a = (unsigned)__cvta_generic_to_shared(spy) + off;
    const unsigned az_a = (unsigned)__cvta_generic_to_shared(spz) + off;
    const unsigned ag_a = (unsigned)__cvta_generic_to_shared(sg2) + off;

    // 8 point-pairs per lane: lane L handles points {2L+64j, 2L+64j+1}
#pragma unroll
    for (int j = 0; j < 8; j++) {
        const ull axx = lds64(ax_a + j * 256);
        const ull ayy = lds64(ay_a + j * 256);
        const ull azz = lds64(az_a + j * 256);
        const ull g22 = lds64(ag_a + j * 256);
#pragma unroll
        for (int r = 0; r < 4; r++) {
            ull t = add2(g22, p22[r]);
            t = fma2(qz2[r], azz, t);
            t = fma2(qy2[r], ayy, t);
            t = fma2(qx2[r], axx, t);             // packed d^2 for 2 points
            tail(t, hC, hB, sh[r], wh[r]);
        }
        if (j == 3) {                             // mid flush: <=4 terms/half
#pragma unroll
            for (int r = 0; r < 4; r++) {
                flush_h2(sh[r], sF[r]);
                flush_h2(wh[r], wF[r]);
            }
        }
    }
#pragma unroll
    for (int r = 0; r < 4; r++) {
        flush_h2(sh[r], sF[r]);
        flush_h2(wh[r], wF[r]);
    }

    // Warp-reduce (s, w) per row; this warp owns (row, slice)
#pragma unroll
    for (int r = 0; r < 4; r++) {
        float s = sF[r], w = wF[r];
#pragma unroll
        for (int o = 16; o; o >>= 1) {
            s += __shfl_xor_sync(0xffffffffu, s, o);
            w += __shfl_xor_sync(0xffffffffu, w, o);
        }
        if (lane == 0) {
            const int row = b * M + m0 + r;
            g_s[row * NSLICES + sl] = s;
            g_w[row * NSLICES + sl] = w;
        }
    }
}

__global__ void emd_combine(void)
{
    __shared__ float sm[16];
    const int row = blockIdx.x * 512 + threadIdx.x;   // 64 x 512 = 32768 rows
    float s = 0.0f, w = 0.0f;
#pragma unroll
    for (int k = 0; k < NSLICES; k++) {
        s += g_s[row * NSLICES + k];
        w += g_w[row * NSLICES + k];
    }
    float val = w / s;                    // per-row softmin-weighted distance
#pragma unroll
    for (int o = 16; o; o >>= 1)
        val += __shfl_xor_sync(0xffffffffu, val, o);
    if ((threadIdx.x & 31) == 0) sm[threadIdx.x >> 5] = val;
    __syncthreads();
    if (threadIdx.x < 16) {
        float v = sm[threadIdx.x];
#pragma unroll
        for (int o = 8; o; o >>= 1)
            v += __shfl_xor_sync(0xffffu, v, o);
        if (threadIdx.x == 0) g_p2[blockIdx.x] = v;
    }
}

__global__ void emd_final(float* __restrict__ out)
{
    __shared__ float sm[2];
    float v = g_p2[threadIdx.x];          // 64 threads
#pragma unroll
    for (int o = 16; o; o >>= 1)
        v += __shfl_xor_sync(0xffffffffu, v, o);
    if ((threadIdx.x & 31) == 0) sm[threadIdx.x >> 5] = v;
    __syncthreads();
    if (threadIdx.x == 0)
        out[0] = (sm[0] + sm[1]) * (1.0f / (float)NROWS);   // LOSS_WEIGHT = 1.0
}

extern "C" void kernel_launch(void* const* d_in, const int* in_sizes, int n_in,
                              void* d_out, int out_size)
{
    const float* pred = (const float*)d_in[0];  // [B, M, 3] fp32
    const float* gt   = (const float*)d_in[1];  // [B, N, 3] fp32
    float* out        = (float*)d_out;          // scalar fp32

    emd_main<<<NBLOCKS, 256>>>(pred, gt);
    emd_combine<<<64, 512>>>();
    emd_final<<<1, 64>>>(out);
}